// round 14
// baseline (speedup 1.0000x reference)
#include <cuda_runtime.h>
#include <math.h>
#include <stdint.h>

// ---------------- problem constants ----------------
#define NBATCH   2
#define NPROP    512
#define NROI     1024            // B * N_PROP
#define CFEAT    256
#define FHW      200
#define PLANE    (FHW*FHW)       // 40000
#define POOLN    7
#define INDIM    (CFEAT*POOLN*POOLN)  // 12544
#define FCDIM    1024
#define NCLS     81
#define NSC      (NPROP*(NCLS-1))    // 40960 per batch
#define NSORT    65536
#define PRENMS   2048
#define NDETS    100
#define CLIPV    4.1351666f      // log(1000/16) rounded to f32
#define KSPLIT1  49              // FC1: klen=256, nK=16, grid 3136 = 10.6 waves (96% eff)
#define KSPLIT2  4               // FC2: klen=256, nK=16

typedef unsigned long long ull;

// ---------------- scratch (device globals; no runtime allocs) ----------------
__device__ float g_featT[NBATCH*PLANE*CFEAT];   // [B,H,W,C] transposed features, 82MB
__device__ float g_X[NROI*INDIM];               // pooled features, 51.4MB
__device__ float g_part[KSPLIT1*NROI*FCDIM];    // split-K partials, 205MB
__device__ float g_H1[NROI*FCDIM];
__device__ float g_H2[NROI*FCDIM];
__device__ float g_logits[NROI*NCLS];
__device__ float g_probs[NROI*NCLS];
__device__ float g_cur[NROI*4];
__device__ unsigned long long g_keys[NBATCH*NSORT];
__device__ float g_selbox[NBATCH*PRENMS*4];
__device__ float g_selval[NBATCH*PRENMS];
__device__ int   g_sellab[NBATCH*PRENMS];
__device__ int   g_Mv[NBATCH];

// ---------------- f32x2 packed helpers (sm_100a) ----------------
__device__ __forceinline__ ull pack2(float x, float y) {
    ull r;
    asm("mov.b64 %0, {%1, %2};" : "=l"(r) : "f"(x), "f"(y));
    return r;
}
__device__ __forceinline__ void fma2(ull& d, ull a, ull b) {
    asm("fma.rn.f32x2 %0, %1, %2, %0;" : "+l"(d) : "l"(a), "l"(b));
}
__device__ __forceinline__ float2 unpack2(ull v) {
    float2 r;
    asm("mov.b64 {%0, %1}, %2;" : "=f"(r.x), "=f"(r.y) : "l"(v));
    return r;
}

// ---------------- utility kernels ----------------
__global__ void zero_out_kernel(float* out, int n) {
    int i = blockIdx.x*blockDim.x + threadIdx.x;
    if (i < n) out[i] = 0.0f;
}

// ---------------- feature transpose: [B,C,H,W] -> [B,H,W,C] ----------------
__global__ void transpose_feat(const float* __restrict__ feat, float* __restrict__ featT)
{
    __shared__ float t[32][33];
    int xt = blockIdx.x * 32, ct = blockIdx.y * 32;
    int by = blockIdx.z;                 // b*FHW + y
    int b = by / FHW, y = by % FHW;
    const float* src = feat + (size_t)b*CFEAT*PLANE + (size_t)y*FHW;
    #pragma unroll
    for (int k = 0; k < 4; k++) {
        int c = ct + threadIdx.y + k*8;
        int x = xt + threadIdx.x;
        if (x < FHW) t[threadIdx.y + k*8][threadIdx.x] = src[(size_t)c*PLANE + x];
    }
    __syncthreads();
    float* dst = featT + (size_t)by*FHW*CFEAT;
    #pragma unroll
    for (int k = 0; k < 4; k++) {
        int x = xt + threadIdx.y + k*8;
        int c = ct + threadIdx.x;
        if (x < FHW) dst[(size_t)x*CFEAT + c] = t[threadIdx.x][threadIdx.y + k*8];
    }
}

// ---------------- RoI align on transposed features, float4 channels ----------------
#define SXROW 260                      // 65 float4 = 260 floats per cell row
__global__ void __launch_bounds__(256)
roi_align_t(const float* __restrict__ featT,
            const float* __restrict__ boxes,
            float* __restrict__ X)
{
    extern __shared__ float sxf[];        // 49*260 floats (50.9KB)
    int r = blockIdx.x;
    int tid = threadIdx.x;
    __shared__ int   soff[4][196];        // premultiplied float4 offsets
    __shared__ float sw  [4][196];
    if (tid < 196) {
        float x1 = boxes[r*4+0]*0.25f, y1 = boxes[r*4+1]*0.25f;
        float x2 = boxes[r*4+2]*0.25f, y2 = boxes[r*4+3]*0.25f;
        float bw = fmaxf(x2-x1, 1.0f) * (1.0f/7.0f);
        float bh = fmaxf(y2-y1, 1.0f) * (1.0f/7.0f);
        int cell = tid >> 2, s = tid & 3;
        int py = cell / 7, px = cell % 7;
        float sy = 0.25f + 0.5f*(float)(s >> 1);
        float sx2 = 0.25f + 0.5f*(float)(s & 1);
        float y = y1 + ((float)py + sy)*bh;
        float x = x1 + ((float)px + sx2)*bw;
        float valid = (y > -1.0f && y < 200.0f && x > -1.0f && x < 200.0f) ? 1.0f : 0.0f;
        y = fminf(fmaxf(y, 0.0f), 199.0f);
        x = fminf(fmaxf(x, 0.0f), 199.0f);
        int y0 = (int)floorf(y), x0 = (int)floorf(x);
        int y1i = min(y0+1, 199), x1i = min(x0+1, 199);
        float ly = y - (float)y0, lx = x - (float)x0;
        float hy = 1.0f - ly, hx = 1.0f - lx;
        const int Q = CFEAT/4;            // 64 float4 per pixel
        soff[0][tid] = (y0 *FHW + x0 )*Q;  sw[0][tid] = hy*hx*valid;
        soff[1][tid] = (y0 *FHW + x1i)*Q;  sw[1][tid] = hy*lx*valid;
        soff[2][tid] = (y1i*FHW + x0 )*Q;  sw[2][tid] = ly*hx*valid;
        soff[3][tid] = (y1i*FHW + x1i)*Q;  sw[3][tid] = ly*lx*valid;
    }
    __syncthreads();
    int b = r >> 9;
    const float4* fb4 = (const float4*)(featT + (size_t)b*PLANE*CFEAT);
    int c4  = tid & 63;                   // float4 channel index
    int grp = tid >> 6;                   // cell group 0..3
    for (int cell = grp; cell < 49; cell += 4) {
        float4 acc = make_float4(0.f, 0.f, 0.f, 0.f);
        #pragma unroll
        for (int s = 0; s < 4; s++) {
            int e = cell*4 + s;
            #pragma unroll
            for (int t = 0; t < 4; t++) {
                float w = sw[t][e];
                float4 v = fb4[soff[t][e] + c4];
                acc.x += w*v.x; acc.y += w*v.y; acc.z += w*v.z; acc.w += w*v.w;
            }
        }
        acc.x *= 0.25f; acc.y *= 0.25f; acc.z *= 0.25f; acc.w *= 0.25f;
        float* dst = sxf + cell*SXROW + c4*4;
        dst[0] = acc.x; dst[1] = acc.y; dst[2] = acc.z; dst[3] = acc.w;
    }
    __syncthreads();
    float* xr = X + (size_t)r*INDIM;
    for (int k = tid; k < INDIM; k += 256) {
        int cc = k / 49, cell = k % 49;
        xr[k] = sxf[cell*SXROW + cc];
    }
}

// ---------------- 128x128x16 split-K SGEMM with f32x2 ----------------
#define BM 128
#define BN 128
#define BK 16

__global__ void __launch_bounds__(256, 2)
sgemm_f32x2_split(const float* __restrict__ A, const float* __restrict__ Bw,
                  float* __restrict__ part, int M, int N, int K, int ksplit)
{
    __shared__ __align__(16) float As[2][BK][BM];
    __shared__ __align__(16) float Bs[2][BK][BN];

    int tid = threadIdx.x;
    int bm = blockIdx.y * BM, bn = blockIdx.x * BN;
    int ks = blockIdx.z;
    int klen = K / ksplit;
    int kof = ks * klen;

    int tx = tid & 15, ty = tid >> 4;
    int m0 = ty << 3;
    int n0 = tx << 3;

    int arow = tid & 127;
    int akq  = (tid >> 7) << 3;
    int brow = tid >> 4;
    int bcol = (tid & 15) << 3;

    const float* Ap = A + (size_t)bm * K + kof;
    const float* Bp = Bw + (size_t)kof * N + bn;

    ull acc[4][8];
    #pragma unroll
    for (int i = 0; i < 4; i++)
        #pragma unroll
        for (int j = 0; j < 8; j++) acc[i][j] = 0ull;

    int nK = klen / BK;

    float4 ra0, ra1, rb0, rb1;
    ra0 = *(const float4*)(Ap + (size_t)arow*K + akq);
    ra1 = *(const float4*)(Ap + (size_t)arow*K + akq + 4);
    rb0 = *(const float4*)(Bp + (size_t)brow*N + bcol);
    rb1 = *(const float4*)(Bp + (size_t)brow*N + bcol + 4);
    As[0][akq+0][arow] = ra0.x; As[0][akq+1][arow] = ra0.y;
    As[0][akq+2][arow] = ra0.z; As[0][akq+3][arow] = ra0.w;
    As[0][akq+4][arow] = ra1.x; As[0][akq+5][arow] = ra1.y;
    As[0][akq+6][arow] = ra1.z; As[0][akq+7][arow] = ra1.w;
    *(float4*)&Bs[0][brow][bcol]   = rb0;
    *(float4*)&Bs[0][brow][bcol+4] = rb1;
    __syncthreads();

    int buf = 0;
    for (int kb = 0; kb < nK; kb++) {
        if (kb + 1 < nK) {
            int k0 = (kb + 1) * BK;
            ra0 = *(const float4*)(Ap + (size_t)arow*K + k0 + akq);
            ra1 = *(const float4*)(Ap + (size_t)arow*K + k0 + akq + 4);
            rb0 = *(const float4*)(Bp + (size_t)(k0 + brow)*N + bcol);
            rb1 = *(const float4*)(Bp + (size_t)(k0 + brow)*N + bcol + 4);
        }
        #pragma unroll
        for (int k = 0; k < BK; k++) {
            float4 af0 = *(const float4*)&As[buf][k][m0];
            float4 af1 = *(const float4*)&As[buf][k][m0+4];
            ull a2[4];
            a2[0] = ((const ull*)&af0)[0];
            a2[1] = ((const ull*)&af0)[1];
            a2[2] = ((const ull*)&af1)[0];
            a2[3] = ((const ull*)&af1)[1];
            float4 bf0 = *(const float4*)&Bs[buf][k][n0];
            float4 bf1 = *(const float4*)&Bs[buf][k][n0+4];
            ull b2[8];
            b2[0] = pack2(bf0.x, bf0.x); b2[1] = pack2(bf0.y, bf0.y);
            b2[2] = pack2(bf0.z, bf0.z); b2[3] = pack2(bf0.w, bf0.w);
            b2[4] = pack2(bf1.x, bf1.x); b2[5] = pack2(bf1.y, bf1.y);
            b2[6] = pack2(bf1.z, bf1.z); b2[7] = pack2(bf1.w, bf1.w);
            #pragma unroll
            for (int i = 0; i < 4; i++) {
                #pragma unroll
                for (int j = 0; j < 8; j++)
                    fma2(acc[i][j], a2[i], b2[j]);
            }
        }
        if (kb + 1 < nK) {
            int nb = buf ^ 1;
            As[nb][akq+0][arow] = ra0.x; As[nb][akq+1][arow] = ra0.y;
            As[nb][akq+2][arow] = ra0.z; As[nb][akq+3][arow] = ra0.w;
            As[nb][akq+4][arow] = ra1.x; As[nb][akq+5][arow] = ra1.y;
            As[nb][akq+6][arow] = ra1.z; As[nb][akq+7][arow] = ra1.w;
            *(float4*)&Bs[nb][brow][bcol]   = rb0;
            *(float4*)&Bs[nb][brow][bcol+4] = rb1;
        }
        __syncthreads();
        buf ^= 1;
    }

    float* Pp = part + (size_t)ks * M * N;
    #pragma unroll
    for (int i = 0; i < 4; i++) {
        float2 u[8];
        #pragma unroll
        for (int j = 0; j < 8; j++) u[j] = unpack2(acc[i][j]);
        float4 e0 = make_float4(u[0].x, u[1].x, u[2].x, u[3].x);
        float4 e1 = make_float4(u[4].x, u[5].x, u[6].x, u[7].x);
        float4 o0 = make_float4(u[0].y, u[1].y, u[2].y, u[3].y);
        float4 o1 = make_float4(u[4].y, u[5].y, u[6].y, u[7].y);
        int row0 = bm + m0 + 2*i;
        float* p0 = Pp + (size_t)row0*N + bn + n0;
        float* p1 = Pp + (size_t)(row0+1)*N + bn + n0;
        *(float4*)(p0)     = e0;
        *(float4*)(p0 + 4) = e1;
        *(float4*)(p1)     = o0;
        *(float4*)(p1 + 4) = o1;
    }
}

// ---------------- split-K reduce (runtime nsplit) ----------------
__global__ void __launch_bounds__(256)
reduce_bias_relu(const float* __restrict__ part, const float* __restrict__ bias,
                 float* __restrict__ C, int M, int N, int doRelu, int nsplit)
{
    int i = blockIdx.x*blockDim.x + threadIdx.x;
    int total = (M*N) >> 2;
    if (i >= total) return;
    size_t stride = (size_t)M*N >> 2;
    const float4* p = (const float4*)part;
    float4 s0 = make_float4(0.f,0.f,0.f,0.f);
    #pragma unroll 4
    for (int s = 0; s < nsplit; s++) {
        float4 v = p[i + (size_t)s*stride];
        s0.x += v.x; s0.y += v.y; s0.z += v.z; s0.w += v.w;
    }
    int col4 = (i << 2) & (N - 1);
    float4 b4 = *(const float4*)(bias + col4);
    float4 r;
    r.x = s0.x + b4.x; r.y = s0.y + b4.y; r.z = s0.z + b4.z; r.w = s0.w + b4.w;
    if (doRelu) {
        r.x = fmaxf(r.x, 0.f); r.y = fmaxf(r.y, 0.f);
        r.z = fmaxf(r.z, 0.f); r.w = fmaxf(r.w, 0.f);
    }
    ((float4*)C)[i] = r;
}

// ---------------- logits head ----------------
__global__ void __launch_bounds__(128)
gemm_logits(const float* __restrict__ H, const float* __restrict__ Wc,
            const float* __restrict__ bc, float* __restrict__ out)
{
    __shared__ float hs[4*1024];
    int m0 = blockIdx.x * 4;
    int t = threadIdx.x;
    const float4* src = (const float4*)(H + (size_t)m0*FCDIM);
    float4* dst = (float4*)hs;
    #pragma unroll
    for (int q = 0; q < 8; q++) dst[q*128 + t] = src[q*128 + t];
    __syncthreads();
    if (t < NCLS) {
        float a0=0, a1=0, a2=0, a3=0;
        for (int k = 0; k < FCDIM; k++) {
            float wv = Wc[k*NCLS + t];
            a0 += hs[k]*wv; a1 += hs[1024+k]*wv; a2 += hs[2048+k]*wv; a3 += hs[3072+k]*wv;
        }
        float bb = bc[t];
        out[(m0+0)*NCLS + t] = a0 + bb;
        out[(m0+1)*NCLS + t] = a1 + bb;
        out[(m0+2)*NCLS + t] = a2 + bb;
        out[(m0+3)*NCLS + t] = a3 + bb;
    }
}

// ---------------- fused delta head + box decode ----------------
// 64 threads: 16 rows x 4 cols; quad shuffle gathers the 4 deltas per row.
__global__ void __launch_bounds__(64)
gemm_deltas_decode(const float* __restrict__ H, const float* __restrict__ Wr,
                   const float* __restrict__ br,
                   const float* __restrict__ curIn, float* __restrict__ curOut,
                   float wx, float wy, float ww, float wh)
{
    int t = threadIdx.x;
    int m0 = blockIdx.x * 16;
    int r = t >> 2, n = t & 3;
    int row = m0 + r;
    const float* hp = H + (size_t)row*FCDIM;
    float a0=0, a1=0, a2=0, a3=0;
    for (int k = 0; k < FCDIM; k += 4) {
        a0 += hp[k+0]*Wr[(k+0)*4+n];
        a1 += hp[k+1]*Wr[(k+1)*4+n];
        a2 += hp[k+2]*Wr[(k+2)*4+n];
        a3 += hp[k+3]*Wr[(k+3)*4+n];
    }
    float d = (a0+a1)+(a2+a3) + br[n];

    unsigned lane = t & 31;
    unsigned base = lane & ~3u;
    float d0 = __shfl_sync(0xffffffffu, d, base + 0);
    float d1 = __shfl_sync(0xffffffffu, d, base + 1);
    float d2 = __shfl_sync(0xffffffffu, d, base + 2);
    float d3 = __shfl_sync(0xffffffffu, d, base + 3);

    if (n == 0) {
        float px1 = curIn[row*4+0], py1 = curIn[row*4+1];
        float px2 = curIn[row*4+2], py2 = curIn[row*4+3];
        float pw = fmaxf(px2 - px1, 1e-6f);
        float ph = fmaxf(py2 - py1, 1e-6f);
        float px = px1 + 0.5f*pw, py = py1 + 0.5f*ph;
        float dx = d0*wx, dy = d1*wy;
        float dw = fminf(d2*ww, CLIPV);
        float dh = fminf(d3*wh, CLIPV);
        float gx = dx*pw + px, gy = dy*ph + py;
        float gw = expf(dw)*pw, gh = expf(dh)*ph;
        curOut[row*4+0] = fminf(fmaxf(gx - 0.5f*gw, 0.0f), 800.0f);
        curOut[row*4+1] = fminf(fmaxf(gy - 0.5f*gh, 0.0f), 800.0f);
        curOut[row*4+2] = fminf(fmaxf(gx + 0.5f*gw, 0.0f), 800.0f);
        curOut[row*4+3] = fminf(fmaxf(gy + 0.5f*gh, 0.0f), 800.0f);
    }
}

// ---------------- softmax over 81 classes ----------------
__global__ void __launch_bounds__(128)
softmax81(const float* __restrict__ logits, float* __restrict__ probs)
{
    int m = blockIdx.x, t = threadIdx.x;
    __shared__ float red[128];
    float v = (t < NCLS) ? logits[m*NCLS + t] : -3.0e38f;
    red[t] = v; __syncthreads();
    for (int s = 64; s > 0; s >>= 1) { if (t < s) red[t] = fmaxf(red[t], red[t+s]); __syncthreads(); }
    float mx = red[0];
    __syncthreads();
    float e = (t < NCLS) ? expf(v - mx) : 0.0f;
    red[t] = e; __syncthreads();
    for (int s = 64; s > 0; s >>= 1) { if (t < s) red[t] += red[t+s]; __syncthreads(); }
    float sum = red[0];
    if (t < NCLS) probs[m*NCLS + t] = e / sum;
}

// ---------------- sort keys ----------------
__global__ void build_keys(const float* __restrict__ probs, const float* __restrict__ boxes,
                           unsigned long long* __restrict__ keys, int* __restrict__ Mv)
{
    int t = blockIdx.x*blockDim.x + threadIdx.x;
    if (t == 0) { Mv[0] = 0; Mv[1] = 0; }
    if (t >= NBATCH*NSORT) return;
    int b = t >> 16, i = t & (NSORT-1);
    unsigned long long key = 0ull;
    if (i < NSC) {
        int roi = i / (NCLS-1);
        int cls = (i % (NCLS-1)) + 1;
        const float* bp = boxes + ((size_t)b*NPROP + roi)*4;
        float ws = bp[2] - bp[0], hs = bp[3] - bp[1];
        float fg = probs[((size_t)b*NPROP + roi)*NCLS + cls];
        unsigned int sb;
        if (fg > 0.05f && ws >= 1.0f && hs >= 1.0f) {
            sb = __float_as_uint(fg) | 0x80000000u;
        } else {
            sb = 0x407FFFFFu;
        }
        key = ((unsigned long long)sb << 32) | (unsigned long long)(0xFFFFFFFFu - (unsigned int)i);
    }
    keys[t] = key;
}

// ---------------- top-2048 selection ----------------
__global__ void __launch_bounds__(1024)
sort_chunks_desc(unsigned long long* __restrict__ keys)
{
    __shared__ unsigned long long sk[2048];
    int chunk = blockIdx.x, b = blockIdx.y;
    unsigned long long* g = keys + (size_t)b*NSORT + (size_t)chunk*2048;
    int tid = threadIdx.x;
    sk[tid] = g[tid]; sk[tid+1024] = g[tid+1024];
    __syncthreads();
    for (int k = 2; k <= 2048; k <<= 1) {
        for (int j = k >> 1; j >= 1; j >>= 1) {
            int i = ((tid & ~(j-1)) << 1) | (tid & (j-1));
            int l = i + j;
            bool up = ((i & k) == 0);
            unsigned long long x = sk[i], y = sk[l];
            if (up ? (x < y) : (x > y)) { sk[i] = y; sk[l] = x; }
            __syncthreads();
        }
    }
    g[tid] = sk[tid]; g[tid+1024] = sk[tid+1024];
}

__global__ void __launch_bounds__(1024)
merge_top2048(unsigned long long* __restrict__ keys, int stride)
{
    __shared__ unsigned long long sk[4096];
    int m = blockIdx.x, b = blockIdx.y;
    int cA = m * 2 * stride;
    int cB = cA + stride;
    unsigned long long* gA = keys + (size_t)b*NSORT + (size_t)cA*2048;
    unsigned long long* gB = keys + (size_t)b*NSORT + (size_t)cB*2048;
    int tid = threadIdx.x;
    sk[tid]        = gA[tid];
    sk[tid + 1024] = gA[tid + 1024];
    sk[4095 - tid]          = gB[tid];
    sk[4095 - (tid + 1024)] = gB[tid + 1024];
    __syncthreads();
    for (int j = 2048; j >= 1; j >>= 1) {
        #pragma unroll
        for (int q = 0; q < 2; q++) {
            int t = tid + q*1024;
            int i = ((t & ~(j-1)) << 1) | (t & (j-1));
            int l = i + j;
            unsigned long long x = sk[i], y = sk[l];
            if (x < y) { sk[i] = y; sk[l] = x; }
        }
        __syncthreads();
    }
    gA[tid]        = sk[tid];
    gA[tid + 1024] = sk[tid + 1024];
}

// ---------------- extract top-2048 per batch ----------------
__global__ void extract_topk(const unsigned long long* __restrict__ keys,
                             const float* __restrict__ boxes,
                             float* __restrict__ selbox, float* __restrict__ selval,
                             int* __restrict__ sellab, int* __restrict__ Mv)
{
    int t = blockIdx.x*blockDim.x + threadIdx.x;
    if (t >= NBATCH*PRENMS) return;
    int b = t >> 11, r = t & (PRENMS-1);
    unsigned long long key = keys[(size_t)b*NSORT + r];
    unsigned int sb = (unsigned int)(key >> 32);
    unsigned int lo = (unsigned int)key;
    float4 bx = make_float4(0,0,0,0);
    int lab = 0; float val = 0.0f;
    if (sb > 0x80000000u) {
        unsigned int idx = 0xFFFFFFFFu - lo;
        int roi = idx / (NCLS-1);
        int cls = idx % (NCLS-1) + 1;
        const float* bp = boxes + ((size_t)b*NPROP + roi)*4;
        bx = make_float4(bp[0], bp[1], bp[2], bp[3]);
        lab = cls;
        val = __uint_as_float(sb & 0x7FFFFFFFu);
        atomicAdd(&Mv[b], 1);
    }
    ((float4*)selbox)[b*PRENMS + r] = bx;
    sellab[b*PRENMS + r] = lab;
    selval[b*PRENMS + r] = val;
}

// ---------------- greedy NMS + output packing ----------------
__global__ void __launch_bounds__(1024)
nms_output(const float* __restrict__ selbox, const float* __restrict__ selval,
           const int* __restrict__ sellab, const int* __restrict__ Mv,
           float* __restrict__ out)
{
    int b = blockIdx.x;
    int tid = threadIdx.x;
    __shared__ float4 sbox[PRENMS];
    __shared__ int    slab[PRENMS];
    __shared__ unsigned char skeep[PRENMS];
    __shared__ int soutidx[NDETS];
    __shared__ int sK;
    int lim = Mv[b]; if (lim > PRENMS) lim = PRENMS;
    for (int r = tid; r < PRENMS; r += 1024) {
        sbox[r] = ((const float4*)selbox)[b*PRENMS + r];
        slab[r] = sellab[b*PRENMS + r];
        skeep[r] = (r < lim) ? 1 : 0;
    }
    __syncthreads();
    int cnt = 0;
    for (int i = 0; i < lim; i++) {
        bool alive = (skeep[i] != 0);
        if (alive) {
            cnt++;
            float4 bi = sbox[i]; int li = slab[i];
            float areaI = (bi.z - bi.x)*(bi.w - bi.y);
            for (int j = i + 1 + tid; j < lim; j += 1024) {
                if (skeep[j] && slab[j] == li) {
                    float4 bj = sbox[j];
                    float ix = fminf(bi.z, bj.z) - fmaxf(bi.x, bj.x);
                    float iy = fminf(bi.w, bj.w) - fmaxf(bi.y, bj.y);
                    float inter = fmaxf(ix, 0.0f)*fmaxf(iy, 0.0f);
                    float areaJ = (bj.z - bj.x)*(bj.w - bj.y);
                    float iou = inter / (areaI + areaJ - inter + 1e-12f);
                    if (iou > 0.5f) skeep[j] = 0;
                }
            }
        }
        __syncthreads();
        if (cnt >= NDETS) break;
    }
    if (tid == 0) {
        int k = 0;
        for (int r = 0; r < lim && k < NDETS; r++)
            if (skeep[r]) soutidx[k++] = r;
        sK = k;
    }
    __syncthreads();
    if (tid < NDETS) {
        float x0=0, y0=0, x1=0, y1=0, sc=0, lb=0;
        if (tid < sK) {
            int r = soutidx[tid];
            float4 bb = sbox[r];
            x0 = bb.x; y0 = bb.y; x1 = bb.z; y1 = bb.w;
            sc = selval[b*PRENMS + r];
            lb = (float)slab[r];
        }
        float* ob = out + (size_t)b*NDETS*4 + tid*4;
        ob[0] = x0; ob[1] = y0; ob[2] = x1; ob[3] = y1;
        out[NBATCH*NDETS*4 + b*NDETS + tid] = sc;
        out[NBATCH*NDETS*4 + NBATCH*NDETS + b*NDETS + tid] = lb;
    }
}

// ---------------- host launch ----------------
extern "C" void kernel_launch(void* const* d_in, const int* in_sizes, int n_in,
                              void* d_out, int out_size)
{
    const float* features  = (const float*)d_in[0];
    const float* proposals = (const float*)d_in[1];
    const float* W1 = (const float*)d_in[2];
    const float* b1 = (const float*)d_in[3];
    const float* W2 = (const float*)d_in[4];
    const float* b2 = (const float*)d_in[5];
    const float* Wc = (const float*)d_in[6];
    const float* bc = (const float*)d_in[7];
    const float* Wr = (const float*)d_in[8];
    const float* br = (const float*)d_in[9];
    float* out = (float*)d_out;

    float *pFT, *pX, *pPart, *pH1, *pH2, *pLg, *pPr, *pCur, *pSelB, *pSelV;
    unsigned long long* pKeys; int *pSelL, *pMv;
    cudaGetSymbolAddress((void**)&pFT,  g_featT);
    cudaGetSymbolAddress((void**)&pX,   g_X);
    cudaGetSymbolAddress((void**)&pPart,g_part);
    cudaGetSymbolAddress((void**)&pH1,  g_H1);
    cudaGetSymbolAddress((void**)&pH2,  g_H2);
    cudaGetSymbolAddress((void**)&pLg,  g_logits);
    cudaGetSymbolAddress((void**)&pPr,  g_probs);
    cudaGetSymbolAddress((void**)&pCur, g_cur);
    cudaGetSymbolAddress((void**)&pKeys,g_keys);
    cudaGetSymbolAddress((void**)&pSelB,g_selbox);
    cudaGetSymbolAddress((void**)&pSelV,g_selval);
    cudaGetSymbolAddress((void**)&pSelL,g_sellab);
    cudaGetSymbolAddress((void**)&pMv,  g_Mv);

    const int ROI_SMEM = 49 * SXROW * (int)sizeof(float);   // 50960 bytes
    cudaFuncSetAttribute(roi_align_t, cudaFuncAttributeMaxDynamicSharedMemorySize, ROI_SMEM);

    zero_out_kernel<<<(out_size + 255)/256, 256>>>(out, out_size);

    // one-time feature transpose [B,C,H,W] -> [B,H,W,C]
    {
        dim3 tg((FHW + 31)/32, CFEAT/32, NBATCH*FHW);   // (7, 8, 400)
        dim3 tb(32, 8);
        transpose_feat<<<tg, tb>>>(features, pFT);
    }

    const float stds[3][4] = {
        {0.1f, 0.1f, 0.2f, 0.2f},
        {0.05f, 0.05f, 0.1f, 0.1f},
        {0.033f, 0.033f, 0.067f, 0.067f}
    };

    dim3 gg1(FCDIM/BN, NROI/BM, KSPLIT1);   // (8, 8, 49) = 3136 blocks, nK=16
    dim3 gg2(FCDIM/BN, NROI/BM, KSPLIT2);   // (8, 8, 4)  = 256 blocks, nK=16
    int redBlocks = (NROI*FCDIM/4 + 255)/256;

    for (int s = 0; s < 3; s++) {
        const float* boxesIn = (s == 0) ? proposals : pCur;

        roi_align_t<<<NROI, 256, ROI_SMEM>>>(pFT, boxesIn, pX);

        sgemm_f32x2_split<<<gg1, 256>>>(pX, W1 + (size_t)s*INDIM*FCDIM, pPart,
                                        NROI, FCDIM, INDIM, KSPLIT1);
        reduce_bias_relu<<<redBlocks, 256>>>(pPart, b1 + s*FCDIM, pH1, NROI, FCDIM, 1, KSPLIT1);

        sgemm_f32x2_split<<<gg2, 256>>>(pH1, W2 + (size_t)s*FCDIM*FCDIM, pPart,
                                        NROI, FCDIM, FCDIM, KSPLIT2);
        reduce_bias_relu<<<redBlocks, 256>>>(pPart, b2 + s*FCDIM, pH2, NROI, FCDIM, 1, KSPLIT2);

        if (s == 2)
            gemm_logits<<<NROI/4, 128>>>(pH2, Wc + (size_t)s*FCDIM*NCLS, bc + s*NCLS, pLg);

        gemm_deltas_decode<<<NROI/16, 64>>>(pH2, Wr + (size_t)s*FCDIM*4, br + s*4,
                                            boxesIn, pCur,
                                            stds[s][0], stds[s][1], stds[s][2], stds[s][3]);
    }

    softmax81<<<NROI, 128>>>(pLg, pPr);
    build_keys<<<(NBATCH*NSORT + 255)/256, 256>>>(pPr, pCur, pKeys, pMv);

    // top-2048 selection: chunk sort + 5 rounds of pairwise top-2048 merges
    sort_chunks_desc<<<dim3(32, NBATCH), 1024>>>(pKeys);
    for (int stride = 1; stride <= 16; stride <<= 1) {
        int nm = 16 / stride;
        merge_top2048<<<dim3(nm, NBATCH), 1024>>>(pKeys, stride);
    }

    extract_topk<<<(NBATCH*PRENMS + 255)/256, 256>>>(pKeys, pCur, pSelB, pSelV, pSelL, pMv);
    nms_output<<<NBATCH, 1024>>>(pSelB, pSelV, pSelL, pMv, out);
}

// round 15
// speedup vs baseline: 1.0762x; 1.0762x over previous
#include <cuda_runtime.h>
#include <math.h>
#include <stdint.h>

// ---------------- problem constants ----------------
#define NBATCH   2
#define NPROP    512
#define NROI     1024            // B * N_PROP
#define CFEAT    256
#define FHW      200
#define PLANE    (FHW*FHW)       // 40000
#define POOLN    7
#define INDIM    (CFEAT*POOLN*POOLN)  // 12544
#define FCDIM    1024
#define NCLS     81
#define NSC      (NPROP*(NCLS-1))    // 40960 per batch
#define NSORT    65536
#define PRENMS   2048
#define NDETS    100
#define CLIPV    4.1351666f      // log(1000/16) rounded to f32
#define KSPLIT1  16              // FC1: klen=784, nK=49 (validated best)
#define KSPLIT2  4               // FC2: klen=256, nK=16

typedef unsigned long long ull;

// ---------------- scratch (device globals; no runtime allocs) ----------------
__device__ float g_featT[NBATCH*PLANE*CFEAT];   // [B,H,W,C] transposed features, 82MB
__device__ float g_X[NROI*INDIM];               // pooled features, 51.4MB
__device__ float g_part[KSPLIT1*NROI*FCDIM];    // split-K partials, 64MB
__device__ float g_H1[NROI*FCDIM];
__device__ float g_H2[NROI*FCDIM];
__device__ float g_logits[NROI*NCLS];
__device__ float g_probs[NROI*NCLS];
__device__ float g_cur[NROI*4];
__device__ unsigned long long g_keys[NBATCH*NSORT];
__device__ float g_selbox[NBATCH*PRENMS*4];
__device__ float g_selval[NBATCH*PRENMS];
__device__ int   g_sellab[NBATCH*PRENMS];
__device__ int   g_Mv[NBATCH];

// ---------------- f32x2 packed helpers (sm_100a) ----------------
__device__ __forceinline__ ull pack2(float x, float y) {
    ull r;
    asm("mov.b64 %0, {%1, %2};" : "=l"(r) : "f"(x), "f"(y));
    return r;
}
__device__ __forceinline__ void fma2(ull& d, ull a, ull b) {
    asm("fma.rn.f32x2 %0, %1, %2, %0;" : "+l"(d) : "l"(a), "l"(b));
}
__device__ __forceinline__ float2 unpack2(ull v) {
    float2 r;
    asm("mov.b64 {%0, %1}, %2;" : "=f"(r.x), "=f"(r.y) : "l"(v));
    return r;
}

// ---------------- utility kernels ----------------
__global__ void zero_out_kernel(float* out, int n) {
    int i = blockIdx.x*blockDim.x + threadIdx.x;
    if (i < n) out[i] = 0.0f;
}

// ---------------- feature transpose: [B,C,H,W] -> [B,H,W,C] ----------------
__global__ void transpose_feat(const float* __restrict__ feat, float* __restrict__ featT)
{
    __shared__ float t[32][33];
    int xt = blockIdx.x * 32, ct = blockIdx.y * 32;
    int by = blockIdx.z;                 // b*FHW + y
    int b = by / FHW, y = by % FHW;
    const float* src = feat + (size_t)b*CFEAT*PLANE + (size_t)y*FHW;
    #pragma unroll
    for (int k = 0; k < 4; k++) {
        int c = ct + threadIdx.y + k*8;
        int x = xt + threadIdx.x;
        if (x < FHW) t[threadIdx.y + k*8][threadIdx.x] = src[(size_t)c*PLANE + x];
    }
    __syncthreads();
    float* dst = featT + (size_t)by*FHW*CFEAT;
    #pragma unroll
    for (int k = 0; k < 4; k++) {
        int x = xt + threadIdx.y + k*8;
        int c = ct + threadIdx.x;
        if (x < FHW) dst[(size_t)x*CFEAT + c] = t[threadIdx.x][threadIdx.y + k*8];
    }
}

// ---------------- RoI align on transposed features, float4 channels ----------------
#define SXROW 260                      // 65 float4 = 260 floats per cell row
__global__ void __launch_bounds__(256)
roi_align_t(const float* __restrict__ featT,
            const float* __restrict__ boxes,
            float* __restrict__ X)
{
    extern __shared__ float sxf[];        // 49*260 floats (50.9KB)
    int r = blockIdx.x;
    int tid = threadIdx.x;
    __shared__ int   soff[4][196];        // premultiplied float4 offsets
    __shared__ float sw  [4][196];
    if (tid < 196) {
        float x1 = boxes[r*4+0]*0.25f, y1 = boxes[r*4+1]*0.25f;
        float x2 = boxes[r*4+2]*0.25f, y2 = boxes[r*4+3]*0.25f;
        float bw = fmaxf(x2-x1, 1.0f) * (1.0f/7.0f);
        float bh = fmaxf(y2-y1, 1.0f) * (1.0f/7.0f);
        int cell = tid >> 2, s = tid & 3;
        int py = cell / 7, px = cell % 7;
        float sy = 0.25f + 0.5f*(float)(s >> 1);
        float sx2 = 0.25f + 0.5f*(float)(s & 1);
        float y = y1 + ((float)py + sy)*bh;
        float x = x1 + ((float)px + sx2)*bw;
        float valid = (y > -1.0f && y < 200.0f && x > -1.0f && x < 200.0f) ? 1.0f : 0.0f;
        y = fminf(fmaxf(y, 0.0f), 199.0f);
        x = fminf(fmaxf(x, 0.0f), 199.0f);
        int y0 = (int)floorf(y), x0 = (int)floorf(x);
        int y1i = min(y0+1, 199), x1i = min(x0+1, 199);
        float ly = y - (float)y0, lx = x - (float)x0;
        float hy = 1.0f - ly, hx = 1.0f - lx;
        const int Q = CFEAT/4;            // 64 float4 per pixel
        soff[0][tid] = (y0 *FHW + x0 )*Q;  sw[0][tid] = hy*hx*valid;
        soff[1][tid] = (y0 *FHW + x1i)*Q;  sw[1][tid] = hy*lx*valid;
        soff[2][tid] = (y1i*FHW + x0 )*Q;  sw[2][tid] = ly*hx*valid;
        soff[3][tid] = (y1i*FHW + x1i)*Q;  sw[3][tid] = ly*lx*valid;
    }
    __syncthreads();
    int b = r >> 9;
    const float4* fb4 = (const float4*)(featT + (size_t)b*PLANE*CFEAT);
    int c4  = tid & 63;                   // float4 channel index
    int grp = tid >> 6;                   // cell group 0..3
    for (int cell = grp; cell < 49; cell += 4) {
        float4 acc = make_float4(0.f, 0.f, 0.f, 0.f);
        #pragma unroll
        for (int s = 0; s < 4; s++) {
            int e = cell*4 + s;
            #pragma unroll
            for (int t = 0; t < 4; t++) {
                float w = sw[t][e];
                float4 v = fb4[soff[t][e] + c4];
                acc.x += w*v.x; acc.y += w*v.y; acc.z += w*v.z; acc.w += w*v.w;
            }
        }
        acc.x *= 0.25f; acc.y *= 0.25f; acc.z *= 0.25f; acc.w *= 0.25f;
        float* dst = sxf + cell*SXROW + c4*4;
        dst[0] = acc.x; dst[1] = acc.y; dst[2] = acc.z; dst[3] = acc.w;
    }
    __syncthreads();
    float* xr = X + (size_t)r*INDIM;
    for (int k = tid; k < INDIM; k += 256) {
        int cc = k / 49, cell = k % 49;
        xr[k] = sxf[cell*SXROW + cc];
    }
}

// ---------------- 128x128x16 split-K SGEMM with f32x2 ----------------
#define BM 128
#define BN 128
#define BK 16

__global__ void __launch_bounds__(256, 2)
sgemm_f32x2_split(const float* __restrict__ A, const float* __restrict__ Bw,
                  float* __restrict__ part, int M, int N, int K, int ksplit)
{
    __shared__ __align__(16) float As[2][BK][BM];
    __shared__ __align__(16) float Bs[2][BK][BN];

    int tid = threadIdx.x;
    int bm = blockIdx.y * BM, bn = blockIdx.x * BN;
    int ks = blockIdx.z;
    int klen = K / ksplit;
    int kof = ks * klen;

    int tx = tid & 15, ty = tid >> 4;
    int m0 = ty << 3;
    int n0 = tx << 3;

    int arow = tid & 127;
    int akq  = (tid >> 7) << 3;
    int brow = tid >> 4;
    int bcol = (tid & 15) << 3;

    const float* Ap = A + (size_t)bm * K + kof;
    const float* Bp = Bw + (size_t)kof * N + bn;

    ull acc[4][8];
    #pragma unroll
    for (int i = 0; i < 4; i++)
        #pragma unroll
        for (int j = 0; j < 8; j++) acc[i][j] = 0ull;

    int nK = klen / BK;

    float4 ra0, ra1, rb0, rb1;
    ra0 = *(const float4*)(Ap + (size_t)arow*K + akq);
    ra1 = *(const float4*)(Ap + (size_t)arow*K + akq + 4);
    rb0 = *(const float4*)(Bp + (size_t)brow*N + bcol);
    rb1 = *(const float4*)(Bp + (size_t)brow*N + bcol + 4);
    As[0][akq+0][arow] = ra0.x; As[0][akq+1][arow] = ra0.y;
    As[0][akq+2][arow] = ra0.z; As[0][akq+3][arow] = ra0.w;
    As[0][akq+4][arow] = ra1.x; As[0][akq+5][arow] = ra1.y;
    As[0][akq+6][arow] = ra1.z; As[0][akq+7][arow] = ra1.w;
    *(float4*)&Bs[0][brow][bcol]   = rb0;
    *(float4*)&Bs[0][brow][bcol+4] = rb1;
    __syncthreads();

    int buf = 0;
    for (int kb = 0; kb < nK; kb++) {
        if (kb + 1 < nK) {
            int k0 = (kb + 1) * BK;
            ra0 = *(const float4*)(Ap + (size_t)arow*K + k0 + akq);
            ra1 = *(const float4*)(Ap + (size_t)arow*K + k0 + akq + 4);
            rb0 = *(const float4*)(Bp + (size_t)(k0 + brow)*N + bcol);
            rb1 = *(const float4*)(Bp + (size_t)(k0 + brow)*N + bcol + 4);
        }
        #pragma unroll
        for (int k = 0; k < BK; k++) {
            float4 af0 = *(const float4*)&As[buf][k][m0];
            float4 af1 = *(const float4*)&As[buf][k][m0+4];
            ull a2[4];
            a2[0] = ((const ull*)&af0)[0];
            a2[1] = ((const ull*)&af0)[1];
            a2[2] = ((const ull*)&af1)[0];
            a2[3] = ((const ull*)&af1)[1];
            float4 bf0 = *(const float4*)&Bs[buf][k][n0];
            float4 bf1 = *(const float4*)&Bs[buf][k][n0+4];
            ull b2[8];
            b2[0] = pack2(bf0.x, bf0.x); b2[1] = pack2(bf0.y, bf0.y);
            b2[2] = pack2(bf0.z, bf0.z); b2[3] = pack2(bf0.w, bf0.w);
            b2[4] = pack2(bf1.x, bf1.x); b2[5] = pack2(bf1.y, bf1.y);
            b2[6] = pack2(bf1.z, bf1.z); b2[7] = pack2(bf1.w, bf1.w);
            #pragma unroll
            for (int i = 0; i < 4; i++) {
                #pragma unroll
                for (int j = 0; j < 8; j++)
                    fma2(acc[i][j], a2[i], b2[j]);
            }
        }
        if (kb + 1 < nK) {
            int nb = buf ^ 1;
            As[nb][akq+0][arow] = ra0.x; As[nb][akq+1][arow] = ra0.y;
            As[nb][akq+2][arow] = ra0.z; As[nb][akq+3][arow] = ra0.w;
            As[nb][akq+4][arow] = ra1.x; As[nb][akq+5][arow] = ra1.y;
            As[nb][akq+6][arow] = ra1.z; As[nb][akq+7][arow] = ra1.w;
            *(float4*)&Bs[nb][brow][bcol]   = rb0;
            *(float4*)&Bs[nb][brow][bcol+4] = rb1;
        }
        __syncthreads();
        buf ^= 1;
    }

    float* Pp = part + (size_t)ks * M * N;
    #pragma unroll
    for (int i = 0; i < 4; i++) {
        float2 u[8];
        #pragma unroll
        for (int j = 0; j < 8; j++) u[j] = unpack2(acc[i][j]);
        float4 e0 = make_float4(u[0].x, u[1].x, u[2].x, u[3].x);
        float4 e1 = make_float4(u[4].x, u[5].x, u[6].x, u[7].x);
        float4 o0 = make_float4(u[0].y, u[1].y, u[2].y, u[3].y);
        float4 o1 = make_float4(u[4].y, u[5].y, u[6].y, u[7].y);
        int row0 = bm + m0 + 2*i;
        float* p0 = Pp + (size_t)row0*N + bn + n0;
        float* p1 = Pp + (size_t)(row0+1)*N + bn + n0;
        *(float4*)(p0)     = e0;
        *(float4*)(p0 + 4) = e1;
        *(float4*)(p1)     = o0;
        *(float4*)(p1 + 4) = o1;
    }
}

// ---------------- split-K reduce (runtime nsplit) ----------------
__global__ void __launch_bounds__(256)
reduce_bias_relu(const float* __restrict__ part, const float* __restrict__ bias,
                 float* __restrict__ C, int M, int N, int doRelu, int nsplit)
{
    int i = blockIdx.x*blockDim.x + threadIdx.x;
    int total = (M*N) >> 2;
    if (i >= total) return;
    size_t stride = (size_t)M*N >> 2;
    const float4* p = (const float4*)part;
    float4 s0 = make_float4(0.f,0.f,0.f,0.f);
    #pragma unroll 4
    for (int s = 0; s < nsplit; s++) {
        float4 v = p[i + (size_t)s*stride];
        s0.x += v.x; s0.y += v.y; s0.z += v.z; s0.w += v.w;
    }
    int col4 = (i << 2) & (N - 1);
    float4 b4 = *(const float4*)(bias + col4);
    float4 r;
    r.x = s0.x + b4.x; r.y = s0.y + b4.y; r.z = s0.z + b4.z; r.w = s0.w + b4.w;
    if (doRelu) {
        r.x = fmaxf(r.x, 0.f); r.y = fmaxf(r.y, 0.f);
        r.z = fmaxf(r.z, 0.f); r.w = fmaxf(r.w, 0.f);
    }
    ((float4*)C)[i] = r;
}

// ---------------- logits head ----------------
__global__ void __launch_bounds__(128)
gemm_logits(const float* __restrict__ H, const float* __restrict__ Wc,
            const float* __restrict__ bc, float* __restrict__ out)
{
    __shared__ float hs[4*1024];
    int m0 = blockIdx.x * 4;
    int t = threadIdx.x;
    const float4* src = (const float4*)(H + (size_t)m0*FCDIM);
    float4* dst = (float4*)hs;
    #pragma unroll
    for (int q = 0; q < 8; q++) dst[q*128 + t] = src[q*128 + t];
    __syncthreads();
    if (t < NCLS) {
        float a0=0, a1=0, a2=0, a3=0;
        for (int k = 0; k < FCDIM; k++) {
            float wv = Wc[k*NCLS + t];
            a0 += hs[k]*wv; a1 += hs[1024+k]*wv; a2 += hs[2048+k]*wv; a3 += hs[3072+k]*wv;
        }
        float bb = bc[t];
        out[(m0+0)*NCLS + t] = a0 + bb;
        out[(m0+1)*NCLS + t] = a1 + bb;
        out[(m0+2)*NCLS + t] = a2 + bb;
        out[(m0+3)*NCLS + t] = a3 + bb;
    }
}

// ---------------- fused delta head + box decode ----------------
__global__ void __launch_bounds__(64)
gemm_deltas_decode(const float* __restrict__ H, const float* __restrict__ Wr,
                   const float* __restrict__ br,
                   const float* __restrict__ curIn, float* __restrict__ curOut,
                   float wx, float wy, float ww, float wh)
{
    int t = threadIdx.x;
    int m0 = blockIdx.x * 16;
    int r = t >> 2, n = t & 3;
    int row = m0 + r;
    const float* hp = H + (size_t)row*FCDIM;
    float a0=0, a1=0, a2=0, a3=0;
    for (int k = 0; k < FCDIM; k += 4) {
        a0 += hp[k+0]*Wr[(k+0)*4+n];
        a1 += hp[k+1]*Wr[(k+1)*4+n];
        a2 += hp[k+2]*Wr[(k+2)*4+n];
        a3 += hp[k+3]*Wr[(k+3)*4+n];
    }
    float d = (a0+a1)+(a2+a3) + br[n];

    unsigned lane = t & 31;
    unsigned base = lane & ~3u;
    float d0 = __shfl_sync(0xffffffffu, d, base + 0);
    float d1 = __shfl_sync(0xffffffffu, d, base + 1);
    float d2 = __shfl_sync(0xffffffffu, d, base + 2);
    float d3 = __shfl_sync(0xffffffffu, d, base + 3);

    if (n == 0) {
        float px1 = curIn[row*4+0], py1 = curIn[row*4+1];
        float px2 = curIn[row*4+2], py2 = curIn[row*4+3];
        float pw = fmaxf(px2 - px1, 1e-6f);
        float ph = fmaxf(py2 - py1, 1e-6f);
        float px = px1 + 0.5f*pw, py = py1 + 0.5f*ph;
        float dx = d0*wx, dy = d1*wy;
        float dw = fminf(d2*ww, CLIPV);
        float dh = fminf(d3*wh, CLIPV);
        float gx = dx*pw + px, gy = dy*ph + py;
        float gw = expf(dw)*pw, gh = expf(dh)*ph;
        curOut[row*4+0] = fminf(fmaxf(gx - 0.5f*gw, 0.0f), 800.0f);
        curOut[row*4+1] = fminf(fmaxf(gy - 0.5f*gh, 0.0f), 800.0f);
        curOut[row*4+2] = fminf(fmaxf(gx + 0.5f*gw, 0.0f), 800.0f);
        curOut[row*4+3] = fminf(fmaxf(gy + 0.5f*gh, 0.0f), 800.0f);
    }
}

// ---------------- softmax over 81 classes ----------------
__global__ void __launch_bounds__(128)
softmax81(const float* __restrict__ logits, float* __restrict__ probs)
{
    int m = blockIdx.x, t = threadIdx.x;
    __shared__ float red[128];
    float v = (t < NCLS) ? logits[m*NCLS + t] : -3.0e38f;
    red[t] = v; __syncthreads();
    for (int s = 64; s > 0; s >>= 1) { if (t < s) red[t] = fmaxf(red[t], red[t+s]); __syncthreads(); }
    float mx = red[0];
    __syncthreads();
    float e = (t < NCLS) ? expf(v - mx) : 0.0f;
    red[t] = e; __syncthreads();
    for (int s = 64; s > 0; s >>= 1) { if (t < s) red[t] += red[t+s]; __syncthreads(); }
    float sum = red[0];
    if (t < NCLS) probs[m*NCLS + t] = e / sum;
}

// ---------------- sort keys ----------------
__global__ void build_keys(const float* __restrict__ probs, const float* __restrict__ boxes,
                           unsigned long long* __restrict__ keys, int* __restrict__ Mv)
{
    int t = blockIdx.x*blockDim.x + threadIdx.x;
    if (t == 0) { Mv[0] = 0; Mv[1] = 0; }
    if (t >= NBATCH*NSORT) return;
    int b = t >> 16, i = t & (NSORT-1);
    unsigned long long key = 0ull;
    if (i < NSC) {
        int roi = i / (NCLS-1);
        int cls = (i % (NCLS-1)) + 1;
        const float* bp = boxes + ((size_t)b*NPROP + roi)*4;
        float ws = bp[2] - bp[0], hs = bp[3] - bp[1];
        float fg = probs[((size_t)b*NPROP + roi)*NCLS + cls];
        unsigned int sb;
        if (fg > 0.05f && ws >= 1.0f && hs >= 1.0f) {
            sb = __float_as_uint(fg) | 0x80000000u;
        } else {
            sb = 0x407FFFFFu;
        }
        key = ((unsigned long long)sb << 32) | (unsigned long long)(0xFFFFFFFFu - (unsigned int)i);
    }
    keys[t] = key;
}

// ---------------- top-2048 selection ----------------
__global__ void __launch_bounds__(1024)
sort_chunks_desc(unsigned long long* __restrict__ keys)
{
    __shared__ unsigned long long sk[2048];
    int chunk = blockIdx.x, b = blockIdx.y;
    unsigned long long* g = keys + (size_t)b*NSORT + (size_t)chunk*2048;
    int tid = threadIdx.x;
    sk[tid] = g[tid]; sk[tid+1024] = g[tid+1024];
    __syncthreads();
    for (int k = 2; k <= 2048; k <<= 1) {
        for (int j = k >> 1; j >= 1; j >>= 1) {
            int i = ((tid & ~(j-1)) << 1) | (tid & (j-1));
            int l = i + j;
            bool up = ((i & k) == 0);
            unsigned long long x = sk[i], y = sk[l];
            if (up ? (x < y) : (x > y)) { sk[i] = y; sk[l] = x; }
            __syncthreads();
        }
    }
    g[tid] = sk[tid]; g[tid+1024] = sk[tid+1024];
}

__global__ void __launch_bounds__(1024)
merge_top2048(unsigned long long* __restrict__ keys, int stride)
{
    __shared__ unsigned long long sk[4096];
    int m = blockIdx.x, b = blockIdx.y;
    int cA = m * 2 * stride;
    int cB = cA + stride;
    unsigned long long* gA = keys + (size_t)b*NSORT + (size_t)cA*2048;
    unsigned long long* gB = keys + (size_t)b*NSORT + (size_t)cB*2048;
    int tid = threadIdx.x;
    sk[tid]        = gA[tid];
    sk[tid + 1024] = gA[tid + 1024];
    sk[4095 - tid]          = gB[tid];
    sk[4095 - (tid + 1024)] = gB[tid + 1024];
    __syncthreads();
    for (int j = 2048; j >= 1; j >>= 1) {
        #pragma unroll
        for (int q = 0; q < 2; q++) {
            int t = tid + q*1024;
            int i = ((t & ~(j-1)) << 1) | (t & (j-1));
            int l = i + j;
            unsigned long long x = sk[i], y = sk[l];
            if (x < y) { sk[i] = y; sk[l] = x; }
        }
        __syncthreads();
    }
    gA[tid]        = sk[tid];
    gA[tid + 1024] = sk[tid + 1024];
}

// ---------------- extract top-2048 per batch ----------------
__global__ void extract_topk(const unsigned long long* __restrict__ keys,
                             const float* __restrict__ boxes,
                             float* __restrict__ selbox, float* __restrict__ selval,
                             int* __restrict__ sellab, int* __restrict__ Mv)
{
    int t = blockIdx.x*blockDim.x + threadIdx.x;
    if (t >= NBATCH*PRENMS) return;
    int b = t >> 11, r = t & (PRENMS-1);
    unsigned long long key = keys[(size_t)b*NSORT + r];
    unsigned int sb = (unsigned int)(key >> 32);
    unsigned int lo = (unsigned int)key;
    float4 bx = make_float4(0,0,0,0);
    int lab = 0; float val = 0.0f;
    if (sb > 0x80000000u) {
        unsigned int idx = 0xFFFFFFFFu - lo;
        int roi = idx / (NCLS-1);
        int cls = idx % (NCLS-1) + 1;
        const float* bp = boxes + ((size_t)b*NPROP + roi)*4;
        bx = make_float4(bp[0], bp[1], bp[2], bp[3]);
        lab = cls;
        val = __uint_as_float(sb & 0x7FFFFFFFu);
        atomicAdd(&Mv[b], 1);
    }
    ((float4*)selbox)[b*PRENMS + r] = bx;
    sellab[b*PRENMS + r] = lab;
    selval[b*PRENMS + r] = val;
}

// ---------------- greedy NMS + output packing ----------------
__global__ void __launch_bounds__(1024)
nms_output(const float* __restrict__ selbox, const float* __restrict__ selval,
           const int* __restrict__ sellab, const int* __restrict__ Mv,
           float* __restrict__ out)
{
    int b = blockIdx.x;
    int tid = threadIdx.x;
    __shared__ float4 sbox[PRENMS];
    __shared__ int    slab[PRENMS];
    __shared__ unsigned char skeep[PRENMS];
    __shared__ int soutidx[NDETS];
    __shared__ int sK;
    int lim = Mv[b]; if (lim > PRENMS) lim = PRENMS;
    for (int r = tid; r < PRENMS; r += 1024) {
        sbox[r] = ((const float4*)selbox)[b*PRENMS + r];
        slab[r] = sellab[b*PRENMS + r];
        skeep[r] = (r < lim) ? 1 : 0;
    }
    __syncthreads();
    int cnt = 0;
    for (int i = 0; i < lim; i++) {
        bool alive = (skeep[i] != 0);
        if (alive) {
            cnt++;
            float4 bi = sbox[i]; int li = slab[i];
            float areaI = (bi.z - bi.x)*(bi.w - bi.y);
            for (int j = i + 1 + tid; j < lim; j += 1024) {
                if (skeep[j] && slab[j] == li) {
                    float4 bj = sbox[j];
                    float ix = fminf(bi.z, bj.z) - fmaxf(bi.x, bj.x);
                    float iy = fminf(bi.w, bj.w) - fmaxf(bi.y, bj.y);
                    float inter = fmaxf(ix, 0.0f)*fmaxf(iy, 0.0f);
                    float areaJ = (bj.z - bj.x)*(bj.w - bj.y);
                    float iou = inter / (areaI + areaJ - inter + 1e-12f);
                    if (iou > 0.5f) skeep[j] = 0;
                }
            }
        }
        __syncthreads();
        if (cnt >= NDETS) break;
    }
    if (tid == 0) {
        int k = 0;
        for (int r = 0; r < lim && k < NDETS; r++)
            if (skeep[r]) soutidx[k++] = r;
        sK = k;
    }
    __syncthreads();
    if (tid < NDETS) {
        float x0=0, y0=0, x1=0, y1=0, sc=0, lb=0;
        if (tid < sK) {
            int r = soutidx[tid];
            float4 bb = sbox[r];
            x0 = bb.x; y0 = bb.y; x1 = bb.z; y1 = bb.w;
            sc = selval[b*PRENMS + r];
            lb = (float)slab[r];
        }
        float* ob = out + (size_t)b*NDETS*4 + tid*4;
        ob[0] = x0; ob[1] = y0; ob[2] = x1; ob[3] = y1;
        out[NBATCH*NDETS*4 + b*NDETS + tid] = sc;
        out[NBATCH*NDETS*4 + NBATCH*NDETS + b*NDETS + tid] = lb;
    }
}

// ---------------- host launch ----------------
extern "C" void kernel_launch(void* const* d_in, const int* in_sizes, int n_in,
                              void* d_out, int out_size)
{
    const float* features  = (const float*)d_in[0];
    const float* proposals = (const float*)d_in[1];
    const float* W1 = (const float*)d_in[2];
    const float* b1 = (const float*)d_in[3];
    const float* W2 = (const float*)d_in[4];
    const float* b2 = (const float*)d_in[5];
    const float* Wc = (const float*)d_in[6];
    const float* bc = (const float*)d_in[7];
    const float* Wr = (const float*)d_in[8];
    const float* br = (const float*)d_in[9];
    float* out = (float*)d_out;

    float *pFT, *pX, *pPart, *pH1, *pH2, *pLg, *pPr, *pCur, *pSelB, *pSelV;
    unsigned long long* pKeys; int *pSelL, *pMv;
    cudaGetSymbolAddress((void**)&pFT,  g_featT);
    cudaGetSymbolAddress((void**)&pX,   g_X);
    cudaGetSymbolAddress((void**)&pPart,g_part);
    cudaGetSymbolAddress((void**)&pH1,  g_H1);
    cudaGetSymbolAddress((void**)&pH2,  g_H2);
    cudaGetSymbolAddress((void**)&pLg,  g_logits);
    cudaGetSymbolAddress((void**)&pPr,  g_probs);
    cudaGetSymbolAddress((void**)&pCur, g_cur);
    cudaGetSymbolAddress((void**)&pKeys,g_keys);
    cudaGetSymbolAddress((void**)&pSelB,g_selbox);
    cudaGetSymbolAddress((void**)&pSelV,g_selval);
    cudaGetSymbolAddress((void**)&pSelL,g_sellab);
    cudaGetSymbolAddress((void**)&pMv,  g_Mv);

    const int ROI_SMEM = 49 * SXROW * (int)sizeof(float);   // 50960 bytes
    cudaFuncSetAttribute(roi_align_t, cudaFuncAttributeMaxDynamicSharedMemorySize, ROI_SMEM);

    zero_out_kernel<<<(out_size + 255)/256, 256>>>(out, out_size);

    // one-time feature transpose [B,C,H,W] -> [B,H,W,C]
    {
        dim3 tg((FHW + 31)/32, CFEAT/32, NBATCH*FHW);   // (7, 8, 400)
        dim3 tb(32, 8);
        transpose_feat<<<tg, tb>>>(features, pFT);
    }

    const float stds[3][4] = {
        {0.1f, 0.1f, 0.2f, 0.2f},
        {0.05f, 0.05f, 0.1f, 0.1f},
        {0.033f, 0.033f, 0.067f, 0.067f}
    };

    dim3 gg1(FCDIM/BN, NROI/BM, KSPLIT1);   // (8, 8, 16) = 1024 blocks, nK=49
    dim3 gg2(FCDIM/BN, NROI/BM, KSPLIT2);   // (8, 8, 4)  = 256 blocks, nK=16
    int redBlocks = (NROI*FCDIM/4 + 255)/256;

    for (int s = 0; s < 3; s++) {
        const float* boxesIn = (s == 0) ? proposals : pCur;

        roi_align_t<<<NROI, 256, ROI_SMEM>>>(pFT, boxesIn, pX);

        sgemm_f32x2_split<<<gg1, 256>>>(pX, W1 + (size_t)s*INDIM*FCDIM, pPart,
                                        NROI, FCDIM, INDIM, KSPLIT1);
        reduce_bias_relu<<<redBlocks, 256>>>(pPart, b1 + s*FCDIM, pH1, NROI, FCDIM, 1, KSPLIT1);

        sgemm_f32x2_split<<<gg2, 256>>>(pH1, W2 + (size_t)s*FCDIM*FCDIM, pPart,
                                        NROI, FCDIM, FCDIM, KSPLIT2);
        reduce_bias_relu<<<redBlocks, 256>>>(pPart, b2 + s*FCDIM, pH2, NROI, FCDIM, 1, KSPLIT2);

        if (s == 2)
            gemm_logits<<<NROI/4, 128>>>(pH2, Wc + (size_t)s*FCDIM*NCLS, bc + s*NCLS, pLg);

        gemm_deltas_decode<<<NROI/16, 64>>>(pH2, Wr + (size_t)s*FCDIM*4, br + s*4,
                                            boxesIn, pCur,
                                            stds[s][0], stds[s][1], stds[s][2], stds[s][3]);
    }

    softmax81<<<NROI, 128>>>(pLg, pPr);
    build_keys<<<(NBATCH*NSORT + 255)/256, 256>>>(pPr, pCur, pKeys, pMv);

    // top-2048 selection: chunk sort + 5 rounds of pairwise top-2048 merges
    sort_chunks_desc<<<dim3(32, NBATCH), 1024>>>(pKeys);
    for (int stride = 1; stride <= 16; stride <<= 1) {
        int nm = 16 / stride;
        merge_top2048<<<dim3(nm, NBATCH), 1024>>>(pKeys, stride);
    }

    extract_topk<<<(NBATCH*PRENMS + 255)/256, 256>>>(pKeys, pCur, pSelB, pSelV, pSelL, pMv);
    nms_output<<<NBATCH, 1024>>>(pSelB, pSelV, pSelL, pMv, out);
}

// round 16
// speedup vs baseline: 1.0969x; 1.0193x over previous
#include <cuda_runtime.h>
#include <math.h>
#include <stdint.h>

// ---------------- problem constants ----------------
#define NBATCH   2
#define NPROP    512
#define NROI     1024            // B * N_PROP
#define CFEAT    256
#define FHW      200
#define PLANE    (FHW*FHW)       // 40000
#define POOLN    7
#define INDIM    (CFEAT*POOLN*POOLN)  // 12544
#define FCDIM    1024
#define NCLS     81
#define NSC      (NPROP*(NCLS-1))    // 40960 per batch
#define NSORT    65536
#define PRENMS   2048
#define NDETS    100
#define CLIPV    4.1351666f      // log(1000/16) rounded to f32
#define KSPLIT1  16              // FC1: klen=784, nK=49 (validated best)
#define KSPLIT2  4               // FC2: klen=256, nK=16

typedef unsigned long long ull;

// ---------------- scratch (device globals; no runtime allocs) ----------------
__device__ float g_featT[NBATCH*PLANE*CFEAT];   // [B,H,W,C] transposed features, 82MB
__device__ float g_X[NROI*INDIM];               // pooled features, 51.4MB
__device__ float g_part[KSPLIT1*NROI*FCDIM];    // split-K partials, 64MB
__device__ float g_H1[NROI*FCDIM];
__device__ float g_H2[NROI*FCDIM];
__device__ float g_logits[NROI*NCLS];
__device__ float g_probs[NROI*NCLS];
__device__ float g_cur[NROI*4];
__device__ unsigned long long g_keys[NBATCH*NSORT];
__device__ float g_selbox[NBATCH*PRENMS*4];
__device__ float g_selval[NBATCH*PRENMS];
__device__ int   g_sellab[NBATCH*PRENMS];
__device__ int   g_Mv[NBATCH];

// ---------------- f32x2 packed helpers (sm_100a) ----------------
__device__ __forceinline__ ull pack2(float x, float y) {
    ull r;
    asm("mov.b64 %0, {%1, %2};" : "=l"(r) : "f"(x), "f"(y));
    return r;
}
__device__ __forceinline__ void fma2(ull& d, ull a, ull b) {
    asm("fma.rn.f32x2 %0, %1, %2, %0;" : "+l"(d) : "l"(a), "l"(b));
}
__device__ __forceinline__ float2 unpack2(ull v) {
    float2 r;
    asm("mov.b64 {%0, %1}, %2;" : "=f"(r.x), "=f"(r.y) : "l"(v));
    return r;
}
// ---------------- cp.async helpers ----------------
__device__ __forceinline__ void cpasync16(void* smem_dst, const void* gsrc) {
    uint32_t s = (uint32_t)__cvta_generic_to_shared(smem_dst);
    asm volatile("cp.async.cg.shared.global [%0], [%1], 16;" :: "r"(s), "l"(gsrc));
}
__device__ __forceinline__ void cpasync_commit() {
    asm volatile("cp.async.commit_group;");
}
__device__ __forceinline__ void cpasync_wait0() {
    asm volatile("cp.async.wait_group 0;");
}

// ---------------- utility kernels ----------------
__global__ void zero_out_kernel(float* out, int n) {
    int i = blockIdx.x*blockDim.x + threadIdx.x;
    if (i < n) out[i] = 0.0f;
}

// ---------------- feature transpose: [B,C,H,W] -> [B,H,W,C] ----------------
__global__ void transpose_feat(const float* __restrict__ feat, float* __restrict__ featT)
{
    __shared__ float t[32][33];
    int xt = blockIdx.x * 32, ct = blockIdx.y * 32;
    int by = blockIdx.z;                 // b*FHW + y
    int b = by / FHW, y = by % FHW;
    const float* src = feat + (size_t)b*CFEAT*PLANE + (size_t)y*FHW;
    #pragma unroll
    for (int k = 0; k < 4; k++) {
        int c = ct + threadIdx.y + k*8;
        int x = xt + threadIdx.x;
        if (x < FHW) t[threadIdx.y + k*8][threadIdx.x] = src[(size_t)c*PLANE + x];
    }
    __syncthreads();
    float* dst = featT + (size_t)by*FHW*CFEAT;
    #pragma unroll
    for (int k = 0; k < 4; k++) {
        int x = xt + threadIdx.y + k*8;
        int c = ct + threadIdx.x;
        if (x < FHW) dst[(size_t)x*CFEAT + c] = t[threadIdx.x][threadIdx.y + k*8];
    }
}

// ---------------- RoI align on transposed features, float4 channels ----------------
#define SXROW 260                      // 65 float4 = 260 floats per cell row
__global__ void __launch_bounds__(256)
roi_align_t(const float* __restrict__ featT,
            const float* __restrict__ boxes,
            float* __restrict__ X)
{
    extern __shared__ float sxf[];        // 49*260 floats (50.9KB)
    int r = blockIdx.x;
    int tid = threadIdx.x;
    __shared__ int   soff[4][196];        // premultiplied float4 offsets
    __shared__ float sw  [4][196];
    if (tid < 196) {
        float x1 = boxes[r*4+0]*0.25f, y1 = boxes[r*4+1]*0.25f;
        float x2 = boxes[r*4+2]*0.25f, y2 = boxes[r*4+3]*0.25f;
        float bw = fmaxf(x2-x1, 1.0f) * (1.0f/7.0f);
        float bh = fmaxf(y2-y1, 1.0f) * (1.0f/7.0f);
        int cell = tid >> 2, s = tid & 3;
        int py = cell / 7, px = cell % 7;
        float sy = 0.25f + 0.5f*(float)(s >> 1);
        float sx2 = 0.25f + 0.5f*(float)(s & 1);
        float y = y1 + ((float)py + sy)*bh;
        float x = x1 + ((float)px + sx2)*bw;
        float valid = (y > -1.0f && y < 200.0f && x > -1.0f && x < 200.0f) ? 1.0f : 0.0f;
        y = fminf(fmaxf(y, 0.0f), 199.0f);
        x = fminf(fmaxf(x, 0.0f), 199.0f);
        int y0 = (int)floorf(y), x0 = (int)floorf(x);
        int y1i = min(y0+1, 199), x1i = min(x0+1, 199);
        float ly = y - (float)y0, lx = x - (float)x0;
        float hy = 1.0f - ly, hx = 1.0f - lx;
        const int Q = CFEAT/4;            // 64 float4 per pixel
        soff[0][tid] = (y0 *FHW + x0 )*Q;  sw[0][tid] = hy*hx*valid;
        soff[1][tid] = (y0 *FHW + x1i)*Q;  sw[1][tid] = hy*lx*valid;
        soff[2][tid] = (y1i*FHW + x0 )*Q;  sw[2][tid] = ly*hx*valid;
        soff[3][tid] = (y1i*FHW + x1i)*Q;  sw[3][tid] = ly*lx*valid;
    }
    __syncthreads();
    int b = r >> 9;
    const float4* fb4 = (const float4*)(featT + (size_t)b*PLANE*CFEAT);
    int c4  = tid & 63;                   // float4 channel index
    int grp = tid >> 6;                   // cell group 0..3
    for (int cell = grp; cell < 49; cell += 4) {
        float4 acc = make_float4(0.f, 0.f, 0.f, 0.f);
        #pragma unroll
        for (int s = 0; s < 4; s++) {
            int e = cell*4 + s;
            #pragma unroll
            for (int t = 0; t < 4; t++) {
                float w = sw[t][e];
                float4 v = fb4[soff[t][e] + c4];
                acc.x += w*v.x; acc.y += w*v.y; acc.z += w*v.z; acc.w += w*v.w;
            }
        }
        acc.x *= 0.25f; acc.y *= 0.25f; acc.z *= 0.25f; acc.w *= 0.25f;
        float* dst = sxf + cell*SXROW + c4*4;
        dst[0] = acc.x; dst[1] = acc.y; dst[2] = acc.z; dst[3] = acc.w;
    }
    __syncthreads();
    // vectorized writeback: float4 over flat X index (gathers from smem)
    float4* xr4 = (float4*)(X + (size_t)r*INDIM);
    for (int k4 = tid; k4 < INDIM/4; k4 += 256) {
        int k = k4 << 2;
        int cc0 = (k+0) / 49, cl0 = (k+0) % 49;
        int cc1 = (k+1) / 49, cl1 = (k+1) % 49;
        int cc2 = (k+2) / 49, cl2 = (k+2) % 49;
        int cc3 = (k+3) / 49, cl3 = (k+3) % 49;
        float4 v;
        v.x = sxf[cl0*SXROW + cc0];
        v.y = sxf[cl1*SXROW + cc1];
        v.z = sxf[cl2*SXROW + cc2];
        v.w = sxf[cl3*SXROW + cc3];
        xr4[k4] = v;
    }
}

// ---------------- 128x128x16 split-K SGEMM with f32x2, cp.async B staging ----------------
#define BM 128
#define BN 128
#define BK 16

__global__ void __launch_bounds__(256, 2)
sgemm_f32x2_split(const float* __restrict__ A, const float* __restrict__ Bw,
                  float* __restrict__ part, int M, int N, int K, int ksplit)
{
    __shared__ __align__(16) float As[2][BK][BM];
    __shared__ __align__(16) float Bs[2][BK][BN];

    int tid = threadIdx.x;
    int bm = blockIdx.y * BM, bn = blockIdx.x * BN;
    int ks = blockIdx.z;
    int klen = K / ksplit;
    int kof = ks * klen;

    int tx = tid & 15, ty = tid >> 4;
    int m0 = ty << 3;
    int n0 = tx << 3;

    int arow = tid & 127;
    int akq  = (tid >> 7) << 3;
    int brow = tid >> 4;
    int bcol = (tid & 15) << 3;

    const float* Ap = A + (size_t)bm * K + kof;
    const float* Bp = Bw + (size_t)kof * N + bn;

    ull acc[4][8];
    #pragma unroll
    for (int i = 0; i < 4; i++)
        #pragma unroll
        for (int j = 0; j < 8; j++) acc[i][j] = 0ull;

    int nK = klen / BK;

    // prologue: B via cp.async, A via LDG+transposed STS
    cpasync16(&Bs[0][brow][bcol],   Bp + (size_t)brow*N + bcol);
    cpasync16(&Bs[0][brow][bcol+4], Bp + (size_t)brow*N + bcol + 4);
    cpasync_commit();
    float4 ra0, ra1;
    ra0 = *(const float4*)(Ap + (size_t)arow*K + akq);
    ra1 = *(const float4*)(Ap + (size_t)arow*K + akq + 4);
    As[0][akq+0][arow] = ra0.x; As[0][akq+1][arow] = ra0.y;
    As[0][akq+2][arow] = ra0.z; As[0][akq+3][arow] = ra0.w;
    As[0][akq+4][arow] = ra1.x; As[0][akq+5][arow] = ra1.y;
    As[0][akq+6][arow] = ra1.z; As[0][akq+7][arow] = ra1.w;
    cpasync_wait0();
    __syncthreads();

    int buf = 0;
    for (int kb = 0; kb < nK; kb++) {
        if (kb + 1 < nK) {
            int k0 = (kb + 1) * BK;
            int nb = buf ^ 1;
            // B for next buffer: async, no registers
            cpasync16(&Bs[nb][brow][bcol],   Bp + (size_t)(k0 + brow)*N + bcol);
            cpasync16(&Bs[nb][brow][bcol+4], Bp + (size_t)(k0 + brow)*N + bcol + 4);
            cpasync_commit();
            // A prefetch into regs (needs transpose on store)
            ra0 = *(const float4*)(Ap + (size_t)arow*K + k0 + akq);
            ra1 = *(const float4*)(Ap + (size_t)arow*K + k0 + akq + 4);
        }
        #pragma unroll
        for (int k = 0; k < BK; k++) {
            float4 af0 = *(const float4*)&As[buf][k][m0];
            float4 af1 = *(const float4*)&As[buf][k][m0+4];
            ull a2[4];
            a2[0] = ((const ull*)&af0)[0];
            a2[1] = ((const ull*)&af0)[1];
            a2[2] = ((const ull*)&af1)[0];
            a2[3] = ((const ull*)&af1)[1];
            float4 bf0 = *(const float4*)&Bs[buf][k][n0];
            float4 bf1 = *(const float4*)&Bs[buf][k][n0+4];
            ull b2[8];
            b2[0] = pack2(bf0.x, bf0.x); b2[1] = pack2(bf0.y, bf0.y);
            b2[2] = pack2(bf0.z, bf0.z); b2[3] = pack2(bf0.w, bf0.w);
            b2[4] = pack2(bf1.x, bf1.x); b2[5] = pack2(bf1.y, bf1.y);
            b2[6] = pack2(bf1.z, bf1.z); b2[7] = pack2(bf1.w, bf1.w);
            #pragma unroll
            for (int i = 0; i < 4; i++) {
                #pragma unroll
                for (int j = 0; j < 8; j++)
                    fma2(acc[i][j], a2[i], b2[j]);
            }
        }
        if (kb + 1 < nK) {
            int nb = buf ^ 1;
            As[nb][akq+0][arow] = ra0.x; As[nb][akq+1][arow] = ra0.y;
            As[nb][akq+2][arow] = ra0.z; As[nb][akq+3][arow] = ra0.w;
            As[nb][akq+4][arow] = ra1.x; As[nb][akq+5][arow] = ra1.y;
            As[nb][akq+6][arow] = ra1.z; As[nb][akq+7][arow] = ra1.w;
            cpasync_wait0();
        }
        __syncthreads();
        buf ^= 1;
    }

    float* Pp = part + (size_t)ks * M * N;
    #pragma unroll
    for (int i = 0; i < 4; i++) {
        float2 u[8];
        #pragma unroll
        for (int j = 0; j < 8; j++) u[j] = unpack2(acc[i][j]);
        float4 e0 = make_float4(u[0].x, u[1].x, u[2].x, u[3].x);
        float4 e1 = make_float4(u[4].x, u[5].x, u[6].x, u[7].x);
        float4 o0 = make_float4(u[0].y, u[1].y, u[2].y, u[3].y);
        float4 o1 = make_float4(u[4].y, u[5].y, u[6].y, u[7].y);
        int row0 = bm + m0 + 2*i;
        float* p0 = Pp + (size_t)row0*N + bn + n0;
        float* p1 = Pp + (size_t)(row0+1)*N + bn + n0;
        *(float4*)(p0)     = e0;
        *(float4*)(p0 + 4) = e1;
        *(float4*)(p1)     = o0;
        *(float4*)(p1 + 4) = o1;
    }
}

// ---------------- split-K reduce (compile-time NS, fully unrolled) ----------------
template<int NS>
__global__ void __launch_bounds__(256)
reduce_bias_relu_t(const float* __restrict__ part, const float* __restrict__ bias,
                   float* __restrict__ C, int M, int N, int doRelu)
{
    int i = blockIdx.x*blockDim.x + threadIdx.x;
    int total = (M*N) >> 2;
    if (i >= total) return;
    size_t stride = (size_t)M*N >> 2;
    const float4* p = (const float4*)part;
    float4 v[NS];
    #pragma unroll
    for (int s = 0; s < NS; s++) v[s] = p[i + (size_t)s*stride];
    float4 s0 = make_float4(0.f,0.f,0.f,0.f);
    #pragma unroll
    for (int s = 0; s < NS; s++) {
        s0.x += v[s].x; s0.y += v[s].y; s0.z += v[s].z; s0.w += v[s].w;
    }
    int col4 = (i << 2) & (N - 1);
    float4 b4 = *(const float4*)(bias + col4);
    float4 r;
    r.x = s0.x + b4.x; r.y = s0.y + b4.y; r.z = s0.z + b4.z; r.w = s0.w + b4.w;
    if (doRelu) {
        r.x = fmaxf(r.x, 0.f); r.y = fmaxf(r.y, 0.f);
        r.z = fmaxf(r.z, 0.f); r.w = fmaxf(r.w, 0.f);
    }
    ((float4*)C)[i] = r;
}

// ---------------- logits head ----------------
__global__ void __launch_bounds__(128)
gemm_logits(const float* __restrict__ H, const float* __restrict__ Wc,
            const float* __restrict__ bc, float* __restrict__ out)
{
    __shared__ float hs[4*1024];
    int m0 = blockIdx.x * 4;
    int t = threadIdx.x;
    const float4* src = (const float4*)(H + (size_t)m0*FCDIM);
    float4* dst = (float4*)hs;
    #pragma unroll
    for (int q = 0; q < 8; q++) dst[q*128 + t] = src[q*128 + t];
    __syncthreads();
    if (t < NCLS) {
        float a0=0, a1=0, a2=0, a3=0;
        for (int k = 0; k < FCDIM; k++) {
            float wv = Wc[k*NCLS + t];
            a0 += hs[k]*wv; a1 += hs[1024+k]*wv; a2 += hs[2048+k]*wv; a3 += hs[3072+k]*wv;
        }
        float bb = bc[t];
        out[(m0+0)*NCLS + t] = a0 + bb;
        out[(m0+1)*NCLS + t] = a1 + bb;
        out[(m0+2)*NCLS + t] = a2 + bb;
        out[(m0+3)*NCLS + t] = a3 + bb;
    }
}

// ---------------- fused delta head + box decode ----------------
__global__ void __launch_bounds__(64)
gemm_deltas_decode(const float* __restrict__ H, const float* __restrict__ Wr,
                   const float* __restrict__ br,
                   const float* __restrict__ curIn, float* __restrict__ curOut,
                   float wx, float wy, float ww, float wh)
{
    int t = threadIdx.x;
    int m0 = blockIdx.x * 16;
    int r = t >> 2, n = t & 3;
    int row = m0 + r;
    const float* hp = H + (size_t)row*FCDIM;
    float a0=0, a1=0, a2=0, a3=0;
    for (int k = 0; k < FCDIM; k += 4) {
        a0 += hp[k+0]*Wr[(k+0)*4+n];
        a1 += hp[k+1]*Wr[(k+1)*4+n];
        a2 += hp[k+2]*Wr[(k+2)*4+n];
        a3 += hp[k+3]*Wr[(k+3)*4+n];
    }
    float d = (a0+a1)+(a2+a3) + br[n];

    unsigned lane = t & 31;
    unsigned base = lane & ~3u;
    float d0 = __shfl_sync(0xffffffffu, d, base + 0);
    float d1 = __shfl_sync(0xffffffffu, d, base + 1);
    float d2 = __shfl_sync(0xffffffffu, d, base + 2);
    float d3 = __shfl_sync(0xffffffffu, d, base + 3);

    if (n == 0) {
        float px1 = curIn[row*4+0], py1 = curIn[row*4+1];
        float px2 = curIn[row*4+2], py2 = curIn[row*4+3];
        float pw = fmaxf(px2 - px1, 1e-6f);
        float ph = fmaxf(py2 - py1, 1e-6f);
        float px = px1 + 0.5f*pw, py = py1 + 0.5f*ph;
        float dx = d0*wx, dy = d1*wy;
        float dw = fminf(d2*ww, CLIPV);
        float dh = fminf(d3*wh, CLIPV);
        float gx = dx*pw + px, gy = dy*ph + py;
        float gw = expf(dw)*pw, gh = expf(dh)*ph;
        curOut[row*4+0] = fminf(fmaxf(gx - 0.5f*gw, 0.0f), 800.0f);
        curOut[row*4+1] = fminf(fmaxf(gy - 0.5f*gh, 0.0f), 800.0f);
        curOut[row*4+2] = fminf(fmaxf(gx + 0.5f*gw, 0.0f), 800.0f);
        curOut[row*4+3] = fminf(fmaxf(gy + 0.5f*gh, 0.0f), 800.0f);
    }
}

// ---------------- softmax over 81 classes ----------------
__global__ void __launch_bounds__(128)
softmax81(const float* __restrict__ logits, float* __restrict__ probs)
{
    int m = blockIdx.x, t = threadIdx.x;
    __shared__ float red[128];
    float v = (t < NCLS) ? logits[m*NCLS + t] : -3.0e38f;
    red[t] = v; __syncthreads();
    for (int s = 64; s > 0; s >>= 1) { if (t < s) red[t] = fmaxf(red[t], red[t+s]); __syncthreads(); }
    float mx = red[0];
    __syncthreads();
    float e = (t < NCLS) ? expf(v - mx) : 0.0f;
    red[t] = e; __syncthreads();
    for (int s = 64; s > 0; s >>= 1) { if (t < s) red[t] += red[t+s]; __syncthreads(); }
    float sum = red[0];
    if (t < NCLS) probs[m*NCLS + t] = e / sum;
}

// ---------------- sort keys ----------------
__global__ void build_keys(const float* __restrict__ probs, const float* __restrict__ boxes,
                           unsigned long long* __restrict__ keys, int* __restrict__ Mv)
{
    int t = blockIdx.x*blockDim.x + threadIdx.x;
    if (t == 0) { Mv[0] = 0; Mv[1] = 0; }
    if (t >= NBATCH*NSORT) return;
    int b = t >> 16, i = t & (NSORT-1);
    unsigned long long key = 0ull;
    if (i < NSC) {
        int roi = i / (NCLS-1);
        int cls = (i % (NCLS-1)) + 1;
        const float* bp = boxes + ((size_t)b*NPROP + roi)*4;
        float ws = bp[2] - bp[0], hs = bp[3] - bp[1];
        float fg = probs[((size_t)b*NPROP + roi)*NCLS + cls];
        unsigned int sb;
        if (fg > 0.05f && ws >= 1.0f && hs >= 1.0f) {
            sb = __float_as_uint(fg) | 0x80000000u;
        } else {
            sb = 0x407FFFFFu;
        }
        key = ((unsigned long long)sb << 32) | (unsigned long long)(0xFFFFFFFFu - (unsigned int)i);
    }
    keys[t] = key;
}

// ---------------- top-2048 selection ----------------
__global__ void __launch_bounds__(1024)
sort_chunks_desc(unsigned long long* __restrict__ keys)
{
    __shared__ unsigned long long sk[2048];
    int chunk = blockIdx.x, b = blockIdx.y;
    unsigned long long* g = keys + (size_t)b*NSORT + (size_t)chunk*2048;
    int tid = threadIdx.x;
    sk[tid] = g[tid]; sk[tid+1024] = g[tid+1024];
    __syncthreads();
    for (int k = 2; k <= 2048; k <<= 1) {
        for (int j = k >> 1; j >= 1; j >>= 1) {
            int i = ((tid & ~(j-1)) << 1) | (tid & (j-1));
            int l = i + j;
            bool up = ((i & k) == 0);
            unsigned long long x = sk[i], y = sk[l];
            if (up ? (x < y) : (x > y)) { sk[i] = y; sk[l] = x; }
            __syncthreads();
        }
    }
    g[tid] = sk[tid]; g[tid+1024] = sk[tid+1024];
}

__global__ void __launch_bounds__(1024)
merge_top2048(unsigned long long* __restrict__ keys, int stride)
{
    __shared__ unsigned long long sk[4096];
    int m = blockIdx.x, b = blockIdx.y;
    int cA = m * 2 * stride;
    int cB = cA + stride;
    unsigned long long* gA = keys + (size_t)b*NSORT + (size_t)cA*2048;
    unsigned long long* gB = keys + (size_t)b*NSORT + (size_t)cB*2048;
    int tid = threadIdx.x;
    sk[tid]        = gA[tid];
    sk[tid + 1024] = gA[tid + 1024];
    sk[4095 - tid]          = gB[tid];
    sk[4095 - (tid + 1024)] = gB[tid + 1024];
    __syncthreads();
    for (int j = 2048; j >= 1; j >>= 1) {
        #pragma unroll
        for (int q = 0; q < 2; q++) {
            int t = tid + q*1024;
            int i = ((t & ~(j-1)) << 1) | (t & (j-1));
            int l = i + j;
            unsigned long long x = sk[i], y = sk[l];
            if (x < y) { sk[i] = y; sk[l] = x; }
        }
        __syncthreads();
    }
    gA[tid]        = sk[tid];
    gA[tid + 1024] = sk[tid + 1024];
}

// ---------------- extract top-2048 per batch ----------------
__global__ void extract_topk(const unsigned long long* __restrict__ keys,
                             const float* __restrict__ boxes,
                             float* __restrict__ selbox, float* __restrict__ selval,
                             int* __restrict__ sellab, int* __restrict__ Mv)
{
    int t = blockIdx.x*blockDim.x + threadIdx.x;
    if (t >= NBATCH*PRENMS) return;
    int b = t >> 11, r = t & (PRENMS-1);
    unsigned long long key = keys[(size_t)b*NSORT + r];
    unsigned int sb = (unsigned int)(key >> 32);
    unsigned int lo = (unsigned int)key;
    float4 bx = make_float4(0,0,0,0);
    int lab = 0; float val = 0.0f;
    if (sb > 0x80000000u) {
        unsigned int idx = 0xFFFFFFFFu - lo;
        int roi = idx / (NCLS-1);
        int cls = idx % (NCLS-1) + 1;
        const float* bp = boxes + ((size_t)b*NPROP + roi)*4;
        bx = make_float4(bp[0], bp[1], bp[2], bp[3]);
        lab = cls;
        val = __uint_as_float(sb & 0x7FFFFFFFu);
        atomicAdd(&Mv[b], 1);
    }
    ((float4*)selbox)[b*PRENMS + r] = bx;
    sellab[b*PRENMS + r] = lab;
    selval[b*PRENMS + r] = val;
}

// ---------------- greedy NMS + output packing ----------------
__global__ void __launch_bounds__(1024)
nms_output(const float* __restrict__ selbox, const float* __restrict__ selval,
           const int* __restrict__ sellab, const int* __restrict__ Mv,
           float* __restrict__ out)
{
    int b = blockIdx.x;
    int tid = threadIdx.x;
    __shared__ float4 sbox[PRENMS];
    __shared__ int    slab[PRENMS];
    __shared__ unsigned char skeep[PRENMS];
    __shared__ int soutidx[NDETS];
    __shared__ int sK;
    int lim = Mv[b]; if (lim > PRENMS) lim = PRENMS;
    for (int r = tid; r < PRENMS; r += 1024) {
        sbox[r] = ((const float4*)selbox)[b*PRENMS + r];
        slab[r] = sellab[b*PRENMS + r];
        skeep[r] = (r < lim) ? 1 : 0;
    }
    __syncthreads();
    int cnt = 0;
    for (int i = 0; i < lim; i++) {
        bool alive = (skeep[i] != 0);
        if (alive) {
            cnt++;
            float4 bi = sbox[i]; int li = slab[i];
            float areaI = (bi.z - bi.x)*(bi.w - bi.y);
            for (int j = i + 1 + tid; j < lim; j += 1024) {
                if (skeep[j] && slab[j] == li) {
                    float4 bj = sbox[j];
                    float ix = fminf(bi.z, bj.z) - fmaxf(bi.x, bj.x);
                    float iy = fminf(bi.w, bj.w) - fmaxf(bi.y, bj.y);
                    float inter = fmaxf(ix, 0.0f)*fmaxf(iy, 0.0f);
                    float areaJ = (bj.z - bj.x)*(bj.w - bj.y);
                    float iou = inter / (areaI + areaJ - inter + 1e-12f);
                    if (iou > 0.5f) skeep[j] = 0;
                }
            }
        }
        __syncthreads();
        if (cnt >= NDETS) break;
    }
    if (tid == 0) {
        int k = 0;
        for (int r = 0; r < lim && k < NDETS; r++)
            if (skeep[r]) soutidx[k++] = r;
        sK = k;
    }
    __syncthreads();
    if (tid < NDETS) {
        float x0=0, y0=0, x1=0, y1=0, sc=0, lb=0;
        if (tid < sK) {
            int r = soutidx[tid];
            float4 bb = sbox[r];
            x0 = bb.x; y0 = bb.y; x1 = bb.z; y1 = bb.w;
            sc = selval[b*PRENMS + r];
            lb = (float)slab[r];
        }
        float* ob = out + (size_t)b*NDETS*4 + tid*4;
        ob[0] = x0; ob[1] = y0; ob[2] = x1; ob[3] = y1;
        out[NBATCH*NDETS*4 + b*NDETS + tid] = sc;
        out[NBATCH*NDETS*4 + NBATCH*NDETS + b*NDETS + tid] = lb;
    }
}

// ---------------- host launch ----------------
extern "C" void kernel_launch(void* const* d_in, const int* in_sizes, int n_in,
                              void* d_out, int out_size)
{
    const float* features  = (const float*)d_in[0];
    const float* proposals = (const float*)d_in[1];
    const float* W1 = (const float*)d_in[2];
    const float* b1 = (const float*)d_in[3];
    const float* W2 = (const float*)d_in[4];
    const float* b2 = (const float*)d_in[5];
    const float* Wc = (const float*)d_in[6];
    const float* bc = (const float*)d_in[7];
    const float* Wr = (const float*)d_in[8];
    const float* br = (const float*)d_in[9];
    float* out = (float*)d_out;

    float *pFT, *pX, *pPart, *pH1, *pH2, *pLg, *pPr, *pCur, *pSelB, *pSelV;
    unsigned long long* pKeys; int *pSelL, *pMv;
    cudaGetSymbolAddress((void**)&pFT,  g_featT);
    cudaGetSymbolAddress((void**)&pX,   g_X);
    cudaGetSymbolAddress((void**)&pPart,g_part);
    cudaGetSymbolAddress((void**)&pH1,  g_H1);
    cudaGetSymbolAddress((void**)&pH2,  g_H2);
    cudaGetSymbolAddress((void**)&pLg,  g_logits);
    cudaGetSymbolAddress((void**)&pPr,  g_probs);
    cudaGetSymbolAddress((void**)&pCur, g_cur);
    cudaGetSymbolAddress((void**)&pKeys,g_keys);
    cudaGetSymbolAddress((void**)&pSelB,g_selbox);
    cudaGetSymbolAddress((void**)&pSelV,g_selval);
    cudaGetSymbolAddress((void**)&pSelL,g_sellab);
    cudaGetSymbolAddress((void**)&pMv,  g_Mv);

    const int ROI_SMEM = 49 * SXROW * (int)sizeof(float);   // 50960 bytes
    cudaFuncSetAttribute(roi_align_t, cudaFuncAttributeMaxDynamicSharedMemorySize, ROI_SMEM);

    zero_out_kernel<<<(out_size + 255)/256, 256>>>(out, out_size);

    // one-time feature transpose [B,C,H,W] -> [B,H,W,C]
    {
        dim3 tg((FHW + 31)/32, CFEAT/32, NBATCH*FHW);   // (7, 8, 400)
        dim3 tb(32, 8);
        transpose_feat<<<tg, tb>>>(features, pFT);
    }

    const float stds[3][4] = {
        {0.1f, 0.1f, 0.2f, 0.2f},
        {0.05f, 0.05f, 0.1f, 0.1f},
        {0.033f, 0.033f, 0.067f, 0.067f}
    };

    dim3 gg1(FCDIM/BN, NROI/BM, KSPLIT1);   // (8, 8, 16) = 1024 blocks, nK=49
    dim3 gg2(FCDIM/BN, NROI/BM, KSPLIT2);   // (8, 8, 4)  = 256 blocks, nK=16
    int redBlocks = (NROI*FCDIM/4 + 255)/256;

    for (int s = 0; s < 3; s++) {
        const float* boxesIn = (s == 0) ? proposals : pCur;

        roi_align_t<<<NROI, 256, ROI_SMEM>>>(pFT, boxesIn, pX);

        sgemm_f32x2_split<<<gg1, 256>>>(pX, W1 + (size_t)s*INDIM*FCDIM, pPart,
                                        NROI, FCDIM, INDIM, KSPLIT1);
        reduce_bias_relu_t<KSPLIT1><<<redBlocks, 256>>>(pPart, b1 + s*FCDIM, pH1,
                                                        NROI, FCDIM, 1);

        sgemm_f32x2_split<<<gg2, 256>>>(pH1, W2 + (size_t)s*FCDIM*FCDIM, pPart,
                                        NROI, FCDIM, FCDIM, KSPLIT2);
        reduce_bias_relu_t<KSPLIT2><<<redBlocks, 256>>>(pPart, b2 + s*FCDIM, pH2,
                                                        NROI, FCDIM, 1);

        if (s == 2)
            gemm_logits<<<NROI/4, 128>>>(pH2, Wc + (size_t)s*FCDIM*NCLS, bc + s*NCLS, pLg);

        gemm_deltas_decode<<<NROI/16, 64>>>(pH2, Wr + (size_t)s*FCDIM*4, br + s*4,
                                            boxesIn, pCur,
                                            stds[s][0], stds[s][1], stds[s][2], stds[s][3]);
    }

    softmax81<<<NROI, 128>>>(pLg, pPr);
    build_keys<<<(NBATCH*NSORT + 255)/256, 256>>>(pPr, pCur, pKeys, pMv);

    // top-2048 selection: chunk sort + 5 rounds of pairwise top-2048 merges
    sort_chunks_desc<<<dim3(32, NBATCH), 1024>>>(pKeys);
    for (int stride = 1; stride <= 16; stride <<= 1) {
        int nm = 16 / stride;
        merge_top2048<<<dim3(nm, NBATCH), 1024>>>(pKeys, stride);
    }

    extract_topk<<<(NBATCH*PRENMS + 255)/256, 256>>>(pKeys, pCur, pSelB, pSelV, pSelL, pMv);
    nms_output<<<NBATCH, 1024>>>(pSelB, pSelV, pSelL, pMv, out);
}